// round 5
// baseline (speedup 1.0000x reference)
#include <cuda_runtime.h>
#include <math.h>

#define NFACES 512
#define HW     256
#define NPIX   (HW*HW)
#define NTEX   (NFACES*64*3)      // 98304
#define TILE   8
#define TPD    32                 // tiles per dimension
#define RBLK   (TPD*TPD)          // 1024 blocks
#define RTPB   256                // 8 warps: 4 face-groups x 64 px
#define PTPB   512                // prep threads

__device__ float4 g_bbox[NFACES];          // sorted by minz
__device__ float4 g_face[NFACES*4];        // sorted: q0,q1,q2,(r,origId,minz,0)
__device__ float  g_tanhTex[NTEX];
__device__ float  g_partials[RBLK];
__device__ unsigned int g_counter;

// ---------------------------------------------------------------------------
// Kernel A: block 0 = face prep + minz rank-sort; blocks 1..48 = texture tanh
// ---------------------------------------------------------------------------
__global__ void __launch_bounds__(PTPB) prep_and_tanh(const float* __restrict__ verts,
                                                      const int*   __restrict__ faces,
                                                      const float* __restrict__ tex) {
    int b = blockIdx.x;
    if (b >= 1) {
        int i = (b - 1) * PTPB + threadIdx.x;   // 24576 float4s over 48 blocks
        float4 v = __ldg(reinterpret_cast<const float4*>(tex) + i);
        v.x = tanhf(v.x); v.y = tanhf(v.y); v.z = tanhf(v.z); v.w = tanhf(v.w);
        reinterpret_cast<float4*>(g_tanhTex)[i] = v;
        return;
    }
    __shared__ float sMzP[NFACES];
    if (threadIdx.x == 0) g_counter = 0;

    int f = threadIdx.x;   // 0..511

    const float ex = 2.732f, ey = 0.0f, ez = -1.6728675276352844e-16f;
    float n  = sqrtf(ex*ex + ey*ey + ez*ez);
    float zx = -ex/n, zy = -ey/n, zz = -ez/n;
    float xx = zz, xy = 0.f, xz = -zx;
    float xn = sqrtf(xx*xx + xy*xy + xz*xz);
    xx /= xn; xy /= xn; xz /= xn;
    float yx = zy*xz - zz*xy;
    float yy = zz*xx - zx*xz;
    float yz = zx*xy - zy*xx;

    int i0 = faces[3*f+0], i1 = faces[3*f+1], i2 = faces[3*f+2];

    float vx, vy, vz;
    vx = verts[3*i0+0]-ex; vy = verts[3*i0+1]-ey; vz = verts[3*i0+2]-ez;
    float ax = vx*xx+vy*xy+vz*xz, ay = vx*yx+vy*yy+vz*yz, az = vx*zx+vy*zy+vz*zz;
    vx = verts[3*i1+0]-ex; vy = verts[3*i1+1]-ey; vz = verts[3*i1+2]-ez;
    float bx = vx*xx+vy*xy+vz*xz, by = vx*yx+vy*yy+vz*yz, bz = vx*zx+vy*zy+vz*zz;
    vx = verts[3*i2+0]-ex; vy = verts[3*i2+1]-ey; vz = verts[3*i2+2]-ez;
    float cx = vx*xx+vy*xy+vz*xz, cy = vx*yx+vy*yy+vz*yz, cz = vx*zx+vy*zy+vz*zz;

    float denom = (bx-ax)*(cy-ay) - (by-ay)*(cx-ax);
    bool deg = (fabsf(denom) <= 1e-8f);
    float minz = deg ? 3.4e38f : fminf(az, fminf(bz, cz));

    sMzP[f] = minz;
    __syncthreads();

    // deterministic rank (ties broken by original index)
    int rank = 0;
    for (int j = 0; j < NFACES; j++) {
        float mj = sMzP[j];
        rank += (mj < minz) || (mj == minz && j < f);
    }

    float o[12];
    float4 bbox;
    float r = 0.f;
    if (deg) {
        #pragma unroll
        for (int k = 0; k < 12; k++) o[k] = 0.f;
        o[2] = -1.f; o[5] = -1.f; o[8] = -1.f;
        bbox = make_float4(2.f, -2.f, 2.f, -2.f);   // empty -> always culled
    } else {
        float s = (denom > 0.f) ? 1.f : -1.f;
        r = 1.0f / fabsf(denom);
        o[0] = s*(by-cy);
        o[1] = s*(cx-bx);
        o[2] = s*((cy-by)*bx - (cx-bx)*by);
        o[3] = s*(cy-ay);
        o[4] = s*(ax-cx);
        o[5] = s*((ay-cy)*cx - (ax-cx)*cy);
        o[6] = s*(ay-by);
        o[7] = s*(bx-ax);
        o[8] = s*((by-ay)*ax - (bx-ax)*ay);
        float D0 = az*r, D1 = bz*r, D2 = cz*r;
        o[9]  = o[0]*D0 + o[3]*D1 + o[6]*D2;   // Dx
        o[10] = o[1]*D0 + o[4]*D1 + o[7]*D2;   // Dy
        o[11] = o[2]*D0 + o[5]*D1 + o[8]*D2;   // Dc
        float xmn = fminf(ax, fminf(bx, cx)) - 1e-6f;
        float xmx = fmaxf(ax, fmaxf(bx, cx)) + 1e-6f;
        float ymn = fminf(ay, fminf(by, cy)) - 1e-6f;
        float ymx = fmaxf(ay, fmaxf(by, cy)) + 1e-6f;
        bbox = make_float4(xmn, xmx, ymn, ymx);
    }
    g_bbox[rank] = bbox;
    float4* dst = &g_face[rank*4];
    dst[0] = make_float4(o[0], o[1], o[2],  o[3]);
    dst[1] = make_float4(o[4], o[5], o[6],  o[7]);
    dst[2] = make_float4(o[8], o[9], o[10], o[11]);
    dst[3] = make_float4(r, (float)f, minz, 0.f);
}

// ---------------------------------------------------------------------------
// Kernel B: 8x8-tile raster, strided 4-way split + sorted-minz early-out
// ---------------------------------------------------------------------------
__global__ void __launch_bounds__(RTPB) raster(const float* __restrict__ ref,
                                               float* __restrict__ out) {
    __shared__ float4 sQ[NFACES*3];        // 24 KB survivor coefficients
    __shared__ float  sMz[NFACES];         // survivor minz (sorted ascending)
    __shared__ float  sR[NFACES];
    __shared__ short  sId[NFACES];         // original face id (texture)
    __shared__ short  sList[NFACES];
    __shared__ int    sWarpCnt[8];
    __shared__ int    sCnt;
    __shared__ float  sBd[4][64];
    __shared__ short  sLi[4][64];
    __shared__ float  sWsum[8];

    const int tid  = threadIdx.x;
    const int lane = tid & 31, w = tid >> 5;

    const int tileX = blockIdx.x & (TPD-1), tileY = blockIdx.x / TPD;
    const int c0 = tileX * TILE, r0 = tileY * TILE;
    const float SC = 2.0f / 256.0f;
    const float tXmin = (c0 + 0.5f) * SC - 1.0f;
    const float tXmax = (c0 + TILE - 0.5f) * SC - 1.0f;
    const float tYmax = 1.0f - (r0 + 0.5f) * SC;
    const float tYmin = 1.0f - (r0 + TILE - 0.5f) * SC;

    if (tid == 0) sCnt = 0;
    __syncthreads();

    // ---- Phase 1: bbox cull + compaction (order-preserving => stays sorted)
    #pragma unroll
    for (int base = 0; base < NFACES; base += RTPB) {
        int f = base + tid;
        float4 bb = __ldg(&g_bbox[f]);
        bool ov = (bb.x <= tXmax) & (bb.y >= tXmin) & (bb.z <= tYmax) & (bb.w >= tYmin);
        unsigned m = __ballot_sync(0xFFFFFFFFu, ov);
        if (lane == 0) sWarpCnt[w] = __popc(m);
        __syncthreads();
        int off = sCnt;
        #pragma unroll
        for (int i = 0; i < 8; i++) if (i < w) off += sWarpCnt[i];
        if (ov) sList[off + __popc(m & ((1u << lane) - 1u))] = (short)f;
        __syncthreads();
        if (tid == 0) {
            int s = 0;
            #pragma unroll
            for (int i = 0; i < 8; i++) s += sWarpCnt[i];
            sCnt += s;
        }
        __syncthreads();
    }
    const int nf = sCnt;

    // ---- Stage survivor coefficients + aux ----
    for (int i = tid; i < nf * 4; i += RTPB) {
        int li = i >> 2, c = i & 3;
        float4 v = __ldg(&g_face[(int)sList[li] * 4 + c]);
        if (c < 3) sQ[li*3 + c] = v;
        else { sR[li] = v.x; sId[li] = (short)v.y; sMz[li] = v.z; }
    }
    __syncthreads();

    // ---- Phase 2: 4 groups x 64 px; group g scans i = g, g+4, ... ----
    const int group = tid >> 6;
    const int sub   = tid & 63;
    const float px = (c0 + (sub & 7) + 0.5f) * SC - 1.0f;
    const float py = 1.0f - (r0 + (sub >> 3) + 0.5f) * SC;

    float bd = __int_as_float(0x7f800000);
    int   li = -1;

    for (int i = group; i < nf; i += 4) {
        float mz = sMz[i];
        if (__all_sync(0xFFFFFFFFu, mz > bd)) break;   // sorted: nothing can win
        float4 q0 = sQ[i*3+0];
        float4 q1 = sQ[i*3+1];
        float4 q2 = sQ[i*3+2];
        float u0 = fmaf(q0.x, px, fmaf(q0.y, py, q0.z));
        float u1 = fmaf(q0.w, px, fmaf(q1.x, py, q1.y));
        float u2 = fmaf(q1.z, px, fmaf(q1.w, py, q2.x));
        float d  = fmaf(q2.y, px, fmaf(q2.z, py, q2.w));
        float m  = fminf(u0, fminf(u1, u2));
        if (m >= 0.f && d > 0.f && d < bd) { bd = d; li = i; }
    }
    sBd[group][sub] = bd;
    sLi[group][sub] = (short)li;
    __syncthreads();

    // ---- Epilogue: merge 4 candidates per pixel, shade, SSE ----
    float acc = 0.f;
    if (tid < 64) {
        float best = sBd[0][tid];
        int   bli  = sLi[0][tid];
        #pragma unroll
        for (int g = 1; g < 4; g++) {
            float dg = sBd[g][tid];
            if (dg < best) { best = dg; bli = sLi[g][tid]; }
        }
        const float qx = (c0 + (tid & 7) + 0.5f) * SC - 1.0f;
        const float qy = 1.0f - (r0 + (tid >> 3) + 0.5f) * SC;
        const int   p  = (r0 + (tid >> 3)) * HW + (c0 + (tid & 7));

        float cc0 = 0.f, cc1 = 0.f, cc2 = 0.f;
        if (bli >= 0) {
            int fo = sId[bli];
            float4 q0 = sQ[bli*3+0];
            float4 q1 = sQ[bli*3+1];
            float  C2 = sQ[bli*3+2].x;
            float  r  = sR[bli];
            float u0 = fmaf(q0.x, qx, fmaf(q0.y, qy, q0.z));
            float u1 = fmaf(q0.w, qx, fmaf(q1.x, qy, q1.y));
            float u2 = fmaf(q1.z, qx, fmaf(q1.w, qy, C2));
            int t0 = min(max((int)rintf(u0 * r * 3.0f), 0), 3);
            int t1 = min(max((int)rintf(u1 * r * 3.0f), 0), 3);
            int t2 = min(max((int)rintf(u2 * r * 3.0f), 0), 3);
            int base = fo*192 + t0*48 + t1*12 + t2*3;
            cc0 = g_tanhTex[base+0];
            cc1 = g_tanhTex[base+1];
            cc2 = g_tanhTex[base+2];
        }
        float e0 = cc0 - __ldg(ref + p);
        float e1 = cc1 - __ldg(ref + p + NPIX);
        float e2 = cc2 - __ldg(ref + p + 2*NPIX);
        acc = fmaf(e0, e0, fmaf(e1, e1, e2*e2));
    }

    // ---- block reduction ----
    #pragma unroll
    for (int o = 16; o > 0; o >>= 1)
        acc += __shfl_down_sync(0xFFFFFFFFu, acc, o);
    if (lane == 0) sWsum[w] = acc;
    __syncthreads();

    // ---- fused deterministic finalize ----
    __shared__ bool sLast;
    if (tid == 0) {
        g_partials[blockIdx.x] = sWsum[0] + sWsum[1];
        __threadfence();
        unsigned t = atomicInc(&g_counter, 0xFFFFFFFFu);
        sLast = (t == RBLK - 1);
    }
    __syncthreads();
    if (sLast) {
        float v = __ldcg(&g_partials[tid])
                + __ldcg(&g_partials[tid + 256])
                + __ldcg(&g_partials[tid + 512])
                + __ldcg(&g_partials[tid + 768]);
        #pragma unroll
        for (int o = 16; o > 0; o >>= 1)
            v += __shfl_down_sync(0xFFFFFFFFu, v, o);
        if (lane == 0) sWsum[w] = v;
        __syncthreads();
        if (tid == 0) {
            float s = 0.f;
            #pragma unroll
            for (int i = 0; i < 8; i++) s += sWsum[i];
            out[0] = s;
        }
    }
}

// ---------------------------------------------------------------------------
extern "C" void kernel_launch(void* const* d_in, const int* in_sizes, int n_in,
                              void* d_out, int out_size) {
    const float* verts = nullptr;
    const float* tex   = nullptr;
    const float* ref   = nullptr;
    const int*   faces = nullptr;
    for (int i = 0; i < n_in; i++) {
        switch (in_sizes[i]) {
            case 1926:   verts = (const float*)d_in[i]; break;
            case 98304:  tex   = (const float*)d_in[i]; break;
            case 196608: ref   = (const float*)d_in[i]; break;
            case 1536:   faces = (const int*)  d_in[i]; break;
            default: break;
        }
    }
    prep_and_tanh<<<49, PTPB>>>(verts, faces, tex);
    raster<<<RBLK, RTPB>>>(ref, (float*)d_out);
}

// round 6
// speedup vs baseline: 1.4961x; 1.4961x over previous
#include <cuda_runtime.h>
#include <math.h>

#define NFACES 512
#define HW     256
#define NPIX   (HW*HW)
#define TILE   8
#define TPD    32                 // tiles per dimension
#define RBLK   (TPD*TPD)          // 1024 blocks
#define RTPB   256                // 8 warps: 4 face-groups x 64 px

__device__ float4   g_face[NFACES*4];   // q0,q1,q2,(r,0,0,0)
__device__ float    g_partials[RBLK];
__device__ unsigned g_counter;          // zero at load; wraps each replay
__device__ unsigned g_ready;            // zero at load; reset in finalize

// ---------------------------------------------------------------------------
// Single fused kernel: prep (blocks 0-1) -> spin -> cull -> raster -> reduce
// ---------------------------------------------------------------------------
__global__ void __launch_bounds__(RTPB) render(const float* __restrict__ verts,
                                               const int*   __restrict__ faces,
                                               const float* __restrict__ tex,
                                               const float* __restrict__ ref,
                                               float*       __restrict__ out) {
    __shared__ float4 sQ[NFACES*3];     // 24 KB survivor coefficients
    __shared__ short  sList[NFACES];    // survivor -> original face id
    __shared__ int    sWarpCnt[8];
    __shared__ int    sCnt;
    __shared__ float  sBd[4][64];
    __shared__ short  sLi[4][64];
    __shared__ float  sWsum[8];

    const int tid  = threadIdx.x;
    const int bid  = blockIdx.x;
    const int lane = tid & 31, w = tid >> 5;

    // ======================= Phase 0: face prep (blocks 0,1) ================
    if (bid < 2) {
        int f = bid * 256 + tid;   // 0..511

        const float ex = 2.732f, ey = 0.0f, ez = -1.6728675276352844e-16f;
        float n  = sqrtf(ex*ex + ey*ey + ez*ez);
        float zx = -ex/n, zy = -ey/n, zz = -ez/n;
        float xx = zz, xy = 0.f, xz = -zx;
        float xn = sqrtf(xx*xx + xy*xy + xz*xz);
        xx /= xn; xy /= xn; xz /= xn;
        float yx = zy*xz - zz*xy;
        float yy = zz*xx - zx*xz;
        float yz = zx*xy - zy*xx;

        int i0 = faces[3*f+0], i1 = faces[3*f+1], i2 = faces[3*f+2];

        float vx, vy, vz;
        vx = verts[3*i0+0]-ex; vy = verts[3*i0+1]-ey; vz = verts[3*i0+2]-ez;
        float ax = vx*xx+vy*xy+vz*xz, ay = vx*yx+vy*yy+vz*yz, az = vx*zx+vy*zy+vz*zz;
        vx = verts[3*i1+0]-ex; vy = verts[3*i1+1]-ey; vz = verts[3*i1+2]-ez;
        float bx = vx*xx+vy*xy+vz*xz, by = vx*yx+vy*yy+vz*yz, bz = vx*zx+vy*zy+vz*zz;
        vx = verts[3*i2+0]-ex; vy = verts[3*i2+1]-ey; vz = verts[3*i2+2]-ez;
        float cx = vx*xx+vy*xy+vz*xz, cy = vx*yx+vy*yy+vz*yz, cz = vx*zx+vy*zy+vz*zz;

        float denom = (bx-ax)*(cy-ay) - (by-ay)*(cx-ax);
        float o[12];
        float r = 0.f;
        if (fabsf(denom) <= 1e-8f) {
            #pragma unroll
            for (int k = 0; k < 12; k++) o[k] = 0.f;
            o[2] = -1.f; o[5] = -1.f; o[8] = -1.f;   // C = -1 -> cull + never inside
        } else {
            float s = (denom > 0.f) ? 1.f : -1.f;
            r = 1.0f / fabsf(denom);
            o[0] = s*(by-cy);                      // A0
            o[1] = s*(cx-bx);                      // B0
            o[2] = s*((cy-by)*bx - (cx-bx)*by);    // C0
            o[3] = s*(cy-ay);                      // A1
            o[4] = s*(ax-cx);                      // B1
            o[5] = s*((ay-cy)*cx - (ax-cx)*cy);    // C1
            o[6] = s*(ay-by);                      // A2
            o[7] = s*(bx-ax);                      // B2
            o[8] = s*((by-ay)*ax - (bx-ax)*ay);    // C2
            float D0 = az*r, D1 = bz*r, D2 = cz*r;
            o[9]  = o[0]*D0 + o[3]*D1 + o[6]*D2;   // Dx
            o[10] = o[1]*D0 + o[4]*D1 + o[7]*D2;   // Dy
            o[11] = o[2]*D0 + o[5]*D1 + o[8]*D2;   // Dc
        }
        float4* dst = &g_face[f*4];
        dst[0] = make_float4(o[0], o[1], o[2],  o[3]);   // A0 B0 C0 A1
        dst[1] = make_float4(o[4], o[5], o[6],  o[7]);   // B1 C1 A2 B2
        dst[2] = make_float4(o[8], o[9], o[10], o[11]);  // C2 Dx Dy Dc
        dst[3] = make_float4(r, 0.f, 0.f, 0.f);
        __threadfence();
        __syncthreads();
        if (tid == 0) atomicAdd(&g_ready, 1u);
    }

    // ======================= Spin until prep published ======================
    if (tid == 0) {
        volatile unsigned* rp = &g_ready;
        while (*rp < 2u) __nanosleep(60);
    }
    if (tid == 0) sCnt = 0;
    __syncthreads();

    // ======================= Tile geometry ==================================
    const int tileX = bid & (TPD-1), tileY = bid / TPD;
    const int c0 = tileX * TILE, r0 = tileY * TILE;
    const float SC = 2.0f / 256.0f;
    const float xc = (c0 + 4.0f) * SC - 1.0f;     // center of pixel-center hull
    const float yc = 1.0f - (r0 + 4.0f) * SC;
    const float hx = 3.5f * SC, hy = 3.5f * SC;   // half-extents of hull

    // ======================= Phase 1: conservative edge cull ================
    #pragma unroll
    for (int base = 0; base < NFACES; base += RTPB) {
        int f = base + tid;
        float4 q0 = __ldcg(&g_face[f*4+0]);
        float4 q1 = __ldcg(&g_face[f*4+1]);
        float4 q2 = __ldcg(&g_face[f*4+2]);
        // max of each affine edge fn over the tile hull; reject if any < 0
        float u0m = fmaf(q0.x, xc, fmaf(q0.y, yc, q0.z)) + fabsf(q0.x)*hx + fabsf(q0.y)*hy;
        float u1m = fmaf(q0.w, xc, fmaf(q1.x, yc, q1.y)) + fabsf(q0.w)*hx + fabsf(q1.x)*hy;
        float u2m = fmaf(q1.z, xc, fmaf(q1.w, yc, q2.x)) + fabsf(q1.z)*hx + fabsf(q1.w)*hy;
        float dm  = fmaf(q2.y, xc, fmaf(q2.z, yc, q2.w)) + fabsf(q2.y)*hx + fabsf(q2.z)*hy;
        bool ov = (u0m >= -1e-5f) & (u1m >= -1e-5f) & (u2m >= -1e-5f) & (dm > -1e-5f);
        unsigned m = __ballot_sync(0xFFFFFFFFu, ov);
        if (lane == 0) sWarpCnt[w] = __popc(m);
        __syncthreads();
        int off = sCnt;
        #pragma unroll
        for (int i = 0; i < 8; i++) if (i < w) off += sWarpCnt[i];
        if (ov) {
            int pos = off + __popc(m & ((1u << lane) - 1u));
            sList[pos] = (short)f;
            sQ[pos*3+0] = q0;           // stage directly from registers
            sQ[pos*3+1] = q1;
            sQ[pos*3+2] = q2;
        }
        __syncthreads();
        if (tid == 0) {
            int s = 0;
            #pragma unroll
            for (int i = 0; i < 8; i++) s += sWarpCnt[i];
            sCnt += s;
        }
        __syncthreads();
    }
    const int nf = sCnt;

    // ======================= Phase 2: 4 groups x 64 px ======================
    const int group = tid >> 6;
    const int sub   = tid & 63;
    const float px = (c0 + (sub & 7) + 0.5f) * SC - 1.0f;
    const float py = 1.0f - (r0 + (sub >> 3) + 0.5f) * SC;

    const int fBeg = (nf * group)     >> 2;
    const int fEnd = (nf * (group+1)) >> 2;

    float bd = __int_as_float(0x7f800000);
    int   li = -1;

    #pragma unroll 4
    for (int i = fBeg; i < fEnd; i++) {
        float4 q0 = sQ[i*3+0];
        float4 q1 = sQ[i*3+1];
        float4 q2 = sQ[i*3+2];
        float u0 = fmaf(q0.x, px, fmaf(q0.y, py, q0.z));
        float u1 = fmaf(q0.w, px, fmaf(q1.x, py, q1.y));
        float u2 = fmaf(q1.z, px, fmaf(q1.w, py, q2.x));
        float d  = fmaf(q2.y, px, fmaf(q2.z, py, q2.w));
        float m  = fminf(u0, fminf(u1, u2));
        if (m >= 0.f && d > 0.f && d < bd) { bd = d; li = i; }
    }
    sBd[group][sub] = bd;
    sLi[group][sub] = (short)li;
    __syncthreads();

    // ======================= Epilogue: merge + shade + SSE ==================
    float acc = 0.f;
    if (tid < 64) {
        float best = sBd[0][tid];
        int   bli  = sLi[0][tid];
        #pragma unroll
        for (int g = 1; g < 4; g++) {
            float dg = sBd[g][tid];
            if (dg < best) { best = dg; bli = sLi[g][tid]; }   // ascending group = argmin
        }
        const float qx = (c0 + (tid & 7) + 0.5f) * SC - 1.0f;
        const float qy = 1.0f - (r0 + (tid >> 3) + 0.5f) * SC;
        const int   p  = (r0 + (tid >> 3)) * HW + (c0 + (tid & 7));

        float cc0 = 0.f, cc1 = 0.f, cc2 = 0.f;
        if (bli >= 0) {
            int fo = sList[bli];
            float4 q0 = sQ[bli*3+0];
            float4 q1 = sQ[bli*3+1];
            float  C2 = sQ[bli*3+2].x;
            float  r  = __ldcg(&g_face[fo*4+3]).x;
            float u0 = fmaf(q0.x, qx, fmaf(q0.y, qy, q0.z));
            float u1 = fmaf(q0.w, qx, fmaf(q1.x, qy, q1.y));
            float u2 = fmaf(q1.z, qx, fmaf(q1.w, qy, C2));
            int t0 = min(max((int)rintf(u0 * r * 3.0f), 0), 3);
            int t1 = min(max((int)rintf(u1 * r * 3.0f), 0), 3);
            int t2 = min(max((int)rintf(u2 * r * 3.0f), 0), 3);
            int base = fo*192 + t0*48 + t1*12 + t2*3;
            cc0 = tanhf(__ldg(tex + base + 0));     // tanh only on the hit texel
            cc1 = tanhf(__ldg(tex + base + 1));
            cc2 = tanhf(__ldg(tex + base + 2));
        }
        float e0 = cc0 - __ldg(ref + p);
        float e1 = cc1 - __ldg(ref + p + NPIX);
        float e2 = cc2 - __ldg(ref + p + 2*NPIX);
        acc = fmaf(e0, e0, fmaf(e1, e1, e2*e2));
    }

    // ======================= Block + grid reduction =========================
    #pragma unroll
    for (int o = 16; o > 0; o >>= 1)
        acc += __shfl_down_sync(0xFFFFFFFFu, acc, o);
    if (lane == 0) sWsum[w] = acc;
    __syncthreads();

    __shared__ bool sLast;
    if (tid == 0) {
        g_partials[bid] = sWsum[0] + sWsum[1];
        __threadfence();
        unsigned t = atomicInc(&g_counter, RBLK - 1);   // wraps to 0 each replay
        sLast = (t == RBLK - 1);
    }
    __syncthreads();
    if (sLast) {
        float v = __ldcg(&g_partials[tid])
                + __ldcg(&g_partials[tid + 256])
                + __ldcg(&g_partials[tid + 512])
                + __ldcg(&g_partials[tid + 768]);
        #pragma unroll
        for (int o = 16; o > 0; o >>= 1)
            v += __shfl_down_sync(0xFFFFFFFFu, v, o);
        if (lane == 0) sWsum[w] = v;
        __syncthreads();
        if (tid == 0) {
            float s = 0.f;
            #pragma unroll
            for (int i = 0; i < 8; i++) s += sWsum[i];
            out[0] = s;
            volatile unsigned* rp = &g_ready;          // reset for next replay
            *rp = 0u;
        }
    }
}

// ---------------------------------------------------------------------------
extern "C" void kernel_launch(void* const* d_in, const int* in_sizes, int n_in,
                              void* d_out, int out_size) {
    const float* verts = nullptr;
    const float* tex   = nullptr;
    const float* ref   = nullptr;
    const int*   faces = nullptr;
    for (int i = 0; i < n_in; i++) {
        switch (in_sizes[i]) {
            case 1926:   verts = (const float*)d_in[i]; break;
            case 98304:  tex   = (const float*)d_in[i]; break;
            case 196608: ref   = (const float*)d_in[i]; break;
            case 1536:   faces = (const int*)  d_in[i]; break;
            default: break;
        }
    }
    render<<<RBLK, RTPB>>>(verts, faces, tex, ref, (float*)d_out);
}

// round 7
// speedup vs baseline: 1.7925x; 1.1981x over previous
#include <cuda_runtime.h>
#include <math.h>

#define NFACES 512
#define HW     256
#define NPIX   (HW*HW)
#define TILE   8
#define TPD    32                 // tiles per dimension
#define RBLK   (TPD*TPD)          // 1024 blocks
#define RTPB   256                // 8 warps: 4 face-groups x 64 px

__device__ float    g_partials[RBLK];
__device__ unsigned g_counter;          // zero at load; wraps each replay

// ---------------------------------------------------------------------------
// Single kernel: per-block register prep + cull -> raster -> reduce
// ---------------------------------------------------------------------------
__global__ void __launch_bounds__(RTPB) render(const float* __restrict__ verts,
                                               const int*   __restrict__ faces,
                                               const float* __restrict__ tex,
                                               const float* __restrict__ ref,
                                               float*       __restrict__ out) {
    __shared__ float4 sQ[NFACES*3];     // 24 KB survivor coefficients
    __shared__ float  sR[NFACES];       // survivor 1/|denom|
    __shared__ short  sList[NFACES];    // survivor -> original face id
    __shared__ int    sWarpCnt[8];
    __shared__ int    sCnt;
    __shared__ float  sBd[4][64];
    __shared__ short  sLi[4][64];
    __shared__ float  sWsum[8];

    const int tid  = threadIdx.x;
    const int bid  = blockIdx.x;
    const int lane = tid & 31, w = tid >> 5;

    // Tile geometry
    const int tileX = bid & (TPD-1), tileY = bid / TPD;
    const int c0 = tileX * TILE, r0 = tileY * TILE;
    const float SC = 2.0f / 256.0f;
    const float xc = (c0 + 4.0f) * SC - 1.0f;     // center of pixel-center hull
    const float yc = 1.0f - (r0 + 4.0f) * SC;
    const float hx = 3.5f * SC, hy = 3.5f * SC;

    // Camera basis (constant-folds: literals)
    const float ex = 2.732f, ey = 0.0f, ez = -1.6728675276352844e-16f;
    const float nrm = sqrtf(ex*ex + ey*ey + ez*ez);
    const float zx = -ex/nrm, zy = -ey/nrm, zz = -ez/nrm;
    float xxu = zz, xyu = 0.f, xzu = -zx;
    const float xn = sqrtf(xxu*xxu + xyu*xyu + xzu*xzu);
    const float xx = xxu/xn, xy = xyu/xn, xz = xzu/xn;
    const float yx = zy*xz - zz*xy;
    const float yy = zz*xx - zx*xz;
    const float yz = zx*xy - zy*xx;

    if (tid == 0) sCnt = 0;
    __syncthreads();

    // ========== Fused prep + conservative edge cull (2 rounds of 256) =======
    #pragma unroll
    for (int base = 0; base < NFACES; base += RTPB) {
        int f = base + tid;

        int i0 = __ldg(&faces[3*f+0]);
        int i1 = __ldg(&faces[3*f+1]);
        int i2 = __ldg(&faces[3*f+2]);

        float vx, vy, vz;
        vx = __ldg(&verts[3*i0+0])-ex; vy = __ldg(&verts[3*i0+1])-ey; vz = __ldg(&verts[3*i0+2])-ez;
        float ax = vx*xx+vy*xy+vz*xz, ay = vx*yx+vy*yy+vz*yz, az = vx*zx+vy*zy+vz*zz;
        vx = __ldg(&verts[3*i1+0])-ex; vy = __ldg(&verts[3*i1+1])-ey; vz = __ldg(&verts[3*i1+2])-ez;
        float bx = vx*xx+vy*xy+vz*xz, by = vx*yx+vy*yy+vz*yz, bz = vx*zx+vy*zy+vz*zz;
        vx = __ldg(&verts[3*i2+0])-ex; vy = __ldg(&verts[3*i2+1])-ey; vz = __ldg(&verts[3*i2+2])-ez;
        float cx = vx*xx+vy*xy+vz*xz, cy = vx*yx+vy*yy+vz*yz, cz = vx*zx+vy*zy+vz*zz;

        float denom = (bx-ax)*(cy-ay) - (by-ay)*(cx-ax);
        bool nondeg = fabsf(denom) > 1e-8f;
        float s = (denom > 0.f) ? 1.f : -1.f;
        float r = nondeg ? (1.0f / fabsf(denom)) : 0.f;

        float A0 = s*(by-cy), B0 = s*(cx-bx), C0 = s*((cy-by)*bx - (cx-bx)*by);
        float A1 = s*(cy-ay), B1 = s*(ax-cx), C1 = s*((ay-cy)*cx - (ax-cx)*cy);
        float A2 = s*(ay-by), B2 = s*(bx-ax), C2 = s*((by-ay)*ax - (bx-ax)*ay);
        float D0 = az*r, D1 = bz*r, D2 = cz*r;
        float Dx = A0*D0 + A1*D1 + A2*D2;
        float Dy = B0*D0 + B1*D1 + B2*D2;
        float Dc = C0*D0 + C1*D1 + C2*D2;

        // conservative per-tile max of each edge fn; reject if any < 0
        float u0m = fmaf(A0, xc, fmaf(B0, yc, C0)) + fabsf(A0)*hx + fabsf(B0)*hy;
        float u1m = fmaf(A1, xc, fmaf(B1, yc, C1)) + fabsf(A1)*hx + fabsf(B1)*hy;
        float u2m = fmaf(A2, xc, fmaf(B2, yc, C2)) + fabsf(A2)*hx + fabsf(B2)*hy;
        float dm  = fmaf(Dx, xc, fmaf(Dy, yc, Dc)) + fabsf(Dx)*hx + fabsf(Dy)*hy;
        bool ov = nondeg & (u0m >= -1e-5f) & (u1m >= -1e-5f) & (u2m >= -1e-5f) & (dm > -1e-5f);

        unsigned m = __ballot_sync(0xFFFFFFFFu, ov);
        if (lane == 0) sWarpCnt[w] = __popc(m);
        __syncthreads();
        int off = sCnt;
        #pragma unroll
        for (int i = 0; i < 8; i++) if (i < w) off += sWarpCnt[i];
        if (ov) {
            int pos = off + __popc(m & ((1u << lane) - 1u));
            sList[pos] = (short)f;
            sR[pos]    = r;
            sQ[pos*3+0] = make_float4(A0, B0, C0, A1);
            sQ[pos*3+1] = make_float4(B1, C1, A2, B2);
            sQ[pos*3+2] = make_float4(C2, Dx, Dy, Dc);
        }
        __syncthreads();
        if (tid == 0) {
            int ssum = 0;
            #pragma unroll
            for (int i = 0; i < 8; i++) ssum += sWarpCnt[i];
            sCnt += ssum;
        }
        __syncthreads();
    }
    const int nf = sCnt;

    // ========== Phase 2: 4 groups x 64 px, contiguous quarters ==============
    const int group = tid >> 6;
    const int sub   = tid & 63;
    const float px = (c0 + (sub & 7) + 0.5f) * SC - 1.0f;
    const float py = 1.0f - (r0 + (sub >> 3) + 0.5f) * SC;

    const int fBeg = (nf * group)     >> 2;
    const int fEnd = (nf * (group+1)) >> 2;

    float bd = __int_as_float(0x7f800000);
    int   li = -1;

    #pragma unroll 4
    for (int i = fBeg; i < fEnd; i++) {
        float4 q0 = sQ[i*3+0];
        float4 q1 = sQ[i*3+1];
        float4 q2 = sQ[i*3+2];
        float u0 = fmaf(q0.x, px, fmaf(q0.y, py, q0.z));
        float u1 = fmaf(q0.w, px, fmaf(q1.x, py, q1.y));
        float u2 = fmaf(q1.z, px, fmaf(q1.w, py, q2.x));
        float d  = fmaf(q2.y, px, fmaf(q2.z, py, q2.w));
        float m  = fminf(u0, fminf(u1, u2));
        if (m >= 0.f && d > 0.f && d < bd) { bd = d; li = i; }
    }
    sBd[group][sub] = bd;
    sLi[group][sub] = (short)li;
    __syncthreads();

    // ========== Epilogue: merge + shade + SSE ===============================
    float acc = 0.f;
    if (tid < 64) {
        float best = sBd[0][tid];
        int   bli  = sLi[0][tid];
        #pragma unroll
        for (int g = 1; g < 4; g++) {
            float dg = sBd[g][tid];
            if (dg < best) { best = dg; bli = sLi[g][tid]; }   // ascending group = argmin
        }
        const float qx = (c0 + (tid & 7) + 0.5f) * SC - 1.0f;
        const float qy = 1.0f - (r0 + (tid >> 3) + 0.5f) * SC;
        const int   p  = (r0 + (tid >> 3)) * HW + (c0 + (tid & 7));

        float cc0 = 0.f, cc1 = 0.f, cc2 = 0.f;
        if (bli >= 0) {
            int fo = sList[bli];
            float4 q0 = sQ[bli*3+0];
            float4 q1 = sQ[bli*3+1];
            float  C2 = sQ[bli*3+2].x;
            float  r  = sR[bli];
            float u0 = fmaf(q0.x, qx, fmaf(q0.y, qy, q0.z));
            float u1 = fmaf(q0.w, qx, fmaf(q1.x, qy, q1.y));
            float u2 = fmaf(q1.z, qx, fmaf(q1.w, qy, C2));
            int t0 = min(max((int)rintf(u0 * r * 3.0f), 0), 3);
            int t1 = min(max((int)rintf(u1 * r * 3.0f), 0), 3);
            int t2 = min(max((int)rintf(u2 * r * 3.0f), 0), 3);
            int base = fo*192 + t0*48 + t1*12 + t2*3;
            cc0 = tanhf(__ldg(tex + base + 0));
            cc1 = tanhf(__ldg(tex + base + 1));
            cc2 = tanhf(__ldg(tex + base + 2));
        }
        float e0 = cc0 - __ldg(ref + p);
        float e1 = cc1 - __ldg(ref + p + NPIX);
        float e2 = cc2 - __ldg(ref + p + 2*NPIX);
        acc = fmaf(e0, e0, fmaf(e1, e1, e2*e2));
    }

    // ========== Block + grid reduction ======================================
    #pragma unroll
    for (int o = 16; o > 0; o >>= 1)
        acc += __shfl_down_sync(0xFFFFFFFFu, acc, o);
    if (lane == 0) sWsum[w] = acc;
    __syncthreads();

    __shared__ bool sLast;
    if (tid == 0) {
        g_partials[bid] = sWsum[0] + sWsum[1];
        __threadfence();
        unsigned t = atomicInc(&g_counter, RBLK - 1);   // wraps to 0 each replay
        sLast = (t == RBLK - 1);
    }
    __syncthreads();
    if (sLast) {
        float v = __ldcg(&g_partials[tid])
                + __ldcg(&g_partials[tid + 256])
                + __ldcg(&g_partials[tid + 512])
                + __ldcg(&g_partials[tid + 768]);
        #pragma unroll
        for (int o = 16; o > 0; o >>= 1)
            v += __shfl_down_sync(0xFFFFFFFFu, v, o);
        if (lane == 0) sWsum[w] = v;
        __syncthreads();
        if (tid == 0) {
            float s = 0.f;
            #pragma unroll
            for (int i = 0; i < 8; i++) s += sWsum[i];
            out[0] = s;
        }
    }
}

// ---------------------------------------------------------------------------
extern "C" void kernel_launch(void* const* d_in, const int* in_sizes, int n_in,
                              void* d_out, int out_size) {
    const float* verts = nullptr;
    const float* tex   = nullptr;
    const float* ref   = nullptr;
    const int*   faces = nullptr;
    for (int i = 0; i < n_in; i++) {
        switch (in_sizes[i]) {
            case 1926:   verts = (const float*)d_in[i]; break;
            case 98304:  tex   = (const float*)d_in[i]; break;
            case 196608: ref   = (const float*)d_in[i]; break;
            case 1536:   faces = (const int*)  d_in[i]; break;
            default: break;
        }
    }
    render<<<RBLK, RTPB>>>(verts, faces, tex, ref, (float*)d_out);
}

// round 8
// speedup vs baseline: 1.8694x; 1.0429x over previous
#include <cuda_runtime.h>
#include <math.h>

#define NFACES 512
#define NVERTS 642
#define HW     256
#define NPIX   (HW*HW)
#define TILE   8
#define TPD    32                 // tiles per dimension
#define RBLK   (TPD*TPD)          // 1024 blocks
#define RTPB   256                // 8 warps; phase2: 8 groups x 32 lanes x 2px

__device__ float    g_partials[RBLK];
__device__ unsigned g_counter;          // zero at load; wraps each replay

// ---------------------------------------------------------------------------
__global__ void __launch_bounds__(RTPB) render(const float* __restrict__ verts,
                                               const int*   __restrict__ faces,
                                               const float* __restrict__ tex,
                                               const float* __restrict__ ref,
                                               float*       __restrict__ out) {
    __shared__ float4 sQ[NFACES*3];     // 24 KB survivor coefficients
    __shared__ float  sR[NFACES];       // survivor 1/|denom|
    __shared__ short  sList[NFACES];    // survivor -> original face id
    __shared__ float4 sU[NVERTS];       // union: verts (phase1) / sBd,sLi (phase2+)
    __shared__ int    sWarpCnt[8];
    __shared__ int    sCnt;
    __shared__ float  sWsum[8];

    float (*sBd)[64] = reinterpret_cast<float(*)[64]>(sU);                 // 8*64*4 = 2KB
    short (*sLi)[64] = reinterpret_cast<short(*)[64]>((char*)sU + 2048);   // 1KB

    const int tid  = threadIdx.x;
    const int bid  = blockIdx.x;
    const int lane = tid & 31, w = tid >> 5;

    // Tile geometry
    const int tileX = bid & (TPD-1), tileY = bid / TPD;
    const int c0 = tileX * TILE, r0 = tileY * TILE;
    const float SC = 2.0f / 256.0f;
    const float xc = (c0 + 4.0f) * SC - 1.0f;
    const float yc = 1.0f - (r0 + 4.0f) * SC;
    const float hx = 3.5f * SC, hy = 3.5f * SC;

    // Camera basis — all compile-time constant-folded
    const float ex = 2.732f, ey = 0.0f, ez = -1.6728675276352844e-16f;
    const float nrm = sqrtf(ex*ex + ey*ey + ez*ez);
    const float zx = -ex/nrm, zy = -ey/nrm, zz = -ez/nrm;
    float xxu = zz, xyu = 0.f, xzu = -zx;
    const float xn = sqrtf(xxu*xxu + xyu*xyu + xzu*xzu);
    const float xx = xxu/xn, xy = xyu/xn, xz = xzu/xn;
    const float yx = zy*xz - zz*xy;
    const float yy = zz*xx - zx*xz;
    const float yz = zx*xy - zy*xx;

    if (tid == 0) sCnt = 0;

    // ========== Stage transformed vertices into SMEM (coalesced) ============
    for (int v = tid; v < NVERTS; v += RTPB) {
        float vx = __ldg(&verts[3*v+0]) - ex;
        float vy = __ldg(&verts[3*v+1]) - ey;
        float vz = __ldg(&verts[3*v+2]) - ez;
        float X = vx*xx + vy*xy + vz*xz;
        float Y = vx*yx + vy*yy + vz*yz;
        float Z = vx*zx + vy*zy + vz*zz;
        sU[v] = make_float4(X, Y, Z, 0.f);
    }
    __syncthreads();

    // ========== Fused prep + conservative edge cull (2 rounds of 256) =======
    #pragma unroll
    for (int base = 0; base < NFACES; base += RTPB) {
        int f = base + tid;
        int i0 = __ldg(&faces[3*f+0]);
        int i1 = __ldg(&faces[3*f+1]);
        int i2 = __ldg(&faces[3*f+2]);

        float4 A = sU[i0];
        float4 B = sU[i1];
        float4 C = sU[i2];
        float ax = A.x, ay = A.y, az = A.z;
        float bx = B.x, by = B.y, bz = B.z;
        float cx = C.x, cy = C.y, cz = C.z;

        float denom = (bx-ax)*(cy-ay) - (by-ay)*(cx-ax);
        bool nondeg = fabsf(denom) > 1e-8f;
        float s = (denom > 0.f) ? 1.f : -1.f;
        float r = nondeg ? (1.0f / fabsf(denom)) : 0.f;

        float A0 = s*(by-cy), B0 = s*(cx-bx), C0 = s*((cy-by)*bx - (cx-bx)*by);
        float A1 = s*(cy-ay), B1 = s*(ax-cx), C1 = s*((ay-cy)*cx - (ax-cx)*cy);
        float A2 = s*(ay-by), B2 = s*(bx-ax), C2 = s*((by-ay)*ax - (bx-ax)*ay);
        float D0 = az*r, D1 = bz*r, D2 = cz*r;
        float Dx = A0*D0 + A1*D1 + A2*D2;
        float Dy = B0*D0 + B1*D1 + B2*D2;
        float Dc = C0*D0 + C1*D1 + C2*D2;

        float u0m = fmaf(A0, xc, fmaf(B0, yc, C0)) + fabsf(A0)*hx + fabsf(B0)*hy;
        float u1m = fmaf(A1, xc, fmaf(B1, yc, C1)) + fabsf(A1)*hx + fabsf(B1)*hy;
        float u2m = fmaf(A2, xc, fmaf(B2, yc, C2)) + fabsf(A2)*hx + fabsf(B2)*hy;
        float dm  = fmaf(Dx, xc, fmaf(Dy, yc, Dc)) + fabsf(Dx)*hx + fabsf(Dy)*hy;
        bool ov = nondeg & (u0m >= -1e-5f) & (u1m >= -1e-5f) & (u2m >= -1e-5f) & (dm > -1e-5f);

        unsigned m = __ballot_sync(0xFFFFFFFFu, ov);
        if (lane == 0) sWarpCnt[w] = __popc(m);
        __syncthreads();
        int off = sCnt;
        #pragma unroll
        for (int i = 0; i < 8; i++) if (i < w) off += sWarpCnt[i];
        if (ov) {
            int pos = off + __popc(m & ((1u << lane) - 1u));
            sList[pos] = (short)f;
            sR[pos]    = r;
            sQ[pos*3+0] = make_float4(A0, B0, C0, A1);
            sQ[pos*3+1] = make_float4(B1, C1, A2, B2);
            sQ[pos*3+2] = make_float4(C2, Dx, Dy, Dc);
        }
        __syncthreads();
        if (tid == 0) {
            int ssum = 0;
            #pragma unroll
            for (int i = 0; i < 8; i++) ssum += sWarpCnt[i];
            sCnt += ssum;
        }
        __syncthreads();
    }
    const int nf = sCnt;

    // ========== Phase 2: 8 warp-groups, 2 px/thread, contiguous eighths =====
    // pair p (=lane): col = (p&3)*2, row = p>>2 ; pixels (col,row),(col+1,row)
    const int pcol = (lane & 3) << 1;
    const int prow = lane >> 2;
    const float px = (c0 + pcol + 0.5f) * SC - 1.0f;
    const float py = 1.0f - (r0 + prow + 0.5f) * SC;

    const int fBeg = (nf * w)     >> 3;
    const int fEnd = (nf * (w+1)) >> 3;

    float bd0 = __int_as_float(0x7f800000), bd1 = bd0;
    int   li0 = -1, li1 = -1;

    #pragma unroll 4
    for (int i = fBeg; i < fEnd; i++) {
        float4 q0 = sQ[i*3+0];
        float4 q1 = sQ[i*3+1];
        float4 q2 = sQ[i*3+2];
        float u0 = fmaf(q0.x, px, fmaf(q0.y, py, q0.z));
        float u1 = fmaf(q0.w, px, fmaf(q1.x, py, q1.y));
        float u2 = fmaf(q1.z, px, fmaf(q1.w, py, q2.x));
        float d0 = fmaf(q2.y, px, fmaf(q2.z, py, q2.w));
        float m0 = fminf(u0, fminf(u1, u2));
        if (m0 >= 0.f && d0 > 0.f && d0 < bd0) { bd0 = d0; li0 = i; }
        float v0 = fmaf(q0.x, SC, u0);
        float v1 = fmaf(q0.w, SC, u1);
        float v2 = fmaf(q1.z, SC, u2);
        float d1 = fmaf(q2.y, SC, d0);
        float m1 = fminf(v0, fminf(v1, v2));
        if (m1 >= 0.f && d1 > 0.f && d1 < bd1) { bd1 = d1; li1 = i; }
    }
    __syncthreads();                 // sU reads done; safe to write sBd/sLi
    {
        int sub = prow * 8 + pcol;
        sBd[w][sub]   = bd0;  sLi[w][sub]   = (short)li0;
        sBd[w][sub+1] = bd1;  sLi[w][sub+1] = (short)li1;
    }
    __syncthreads();

    // ========== Epilogue: merge 8 candidates + shade + SSE ==================
    float acc = 0.f;
    if (tid < 64) {
        float best = sBd[0][tid];
        int   bli  = sLi[0][tid];
        #pragma unroll
        for (int g = 1; g < 8; g++) {
            float dg = sBd[g][tid];
            if (dg < best) { best = dg; bli = sLi[g][tid]; }   // ascending group = argmin
        }
        const float qx = (c0 + (tid & 7) + 0.5f) * SC - 1.0f;
        const float qy = 1.0f - (r0 + (tid >> 3) + 0.5f) * SC;
        const int   p  = (r0 + (tid >> 3)) * HW + (c0 + (tid & 7));

        float cc0 = 0.f, cc1 = 0.f, cc2 = 0.f;
        if (bli >= 0) {
            int fo = sList[bli];
            float4 q0 = sQ[bli*3+0];
            float4 q1 = sQ[bli*3+1];
            float  C2 = sQ[bli*3+2].x;
            float  r  = sR[bli];
            float u0 = fmaf(q0.x, qx, fmaf(q0.y, qy, q0.z));
            float u1 = fmaf(q0.w, qx, fmaf(q1.x, qy, q1.y));
            float u2 = fmaf(q1.z, qx, fmaf(q1.w, qy, C2));
            int t0 = min(max((int)rintf(u0 * r * 3.0f), 0), 3);
            int t1 = min(max((int)rintf(u1 * r * 3.0f), 0), 3);
            int t2 = min(max((int)rintf(u2 * r * 3.0f), 0), 3);
            int base = fo*192 + t0*48 + t1*12 + t2*3;
            cc0 = tanhf(__ldg(tex + base + 0));
            cc1 = tanhf(__ldg(tex + base + 1));
            cc2 = tanhf(__ldg(tex + base + 2));
        }
        float e0 = cc0 - __ldg(ref + p);
        float e1 = cc1 - __ldg(ref + p + NPIX);
        float e2 = cc2 - __ldg(ref + p + 2*NPIX);
        acc = fmaf(e0, e0, fmaf(e1, e1, e2*e2));
    }

    // ========== Block + grid reduction ======================================
    #pragma unroll
    for (int o = 16; o > 0; o >>= 1)
        acc += __shfl_down_sync(0xFFFFFFFFu, acc, o);
    if (lane == 0) sWsum[w] = acc;
    __syncthreads();

    __shared__ bool sLast;
    if (tid == 0) {
        g_partials[bid] = sWsum[0] + sWsum[1];
        __threadfence();
        unsigned t = atomicInc(&g_counter, RBLK - 1);   // wraps each replay
        sLast = (t == RBLK - 1);
    }
    __syncthreads();
    if (sLast) {
        float v = __ldcg(&g_partials[tid])
                + __ldcg(&g_partials[tid + 256])
                + __ldcg(&g_partials[tid + 512])
                + __ldcg(&g_partials[tid + 768]);
        #pragma unroll
        for (int o = 16; o > 0; o >>= 1)
            v += __shfl_down_sync(0xFFFFFFFFu, v, o);
        if (lane == 0) sWsum[w] = v;
        __syncthreads();
        if (tid == 0) {
            float s = 0.f;
            #pragma unroll
            for (int i = 0; i < 8; i++) s += sWsum[i];
            out[0] = s;
        }
    }
}

// ---------------------------------------------------------------------------
extern "C" void kernel_launch(void* const* d_in, const int* in_sizes, int n_in,
                              void* d_out, int out_size) {
    const float* verts = nullptr;
    const float* tex   = nullptr;
    const float* ref   = nullptr;
    const int*   faces = nullptr;
    for (int i = 0; i < n_in; i++) {
        switch (in_sizes[i]) {
            case 1926:   verts = (const float*)d_in[i]; break;
            case 98304:  tex   = (const float*)d_in[i]; break;
            case 196608: ref   = (const float*)d_in[i]; break;
            case 1536:   faces = (const int*)  d_in[i]; break;
            default: break;
        }
    }
    render<<<RBLK, RTPB>>>(verts, faces, tex, ref, (float*)d_out);
}

// round 9
// speedup vs baseline: 2.0713x; 1.1080x over previous
#include <cuda_runtime.h>
#include <math.h>

#define NFACES 512
#define NVERTS 642
#define HW     256
#define NPIX   (HW*HW)
#define TILE   8
#define TPD    32                 // tiles per dimension
#define RBLK   (TPD*TPD)          // 1024 blocks
#define RTPB   256                // 8 warps; phase2: 8 groups x 32 lanes x 2px

__device__ float    g_partials[RBLK];
__device__ unsigned g_counter;          // zero at load; wraps each replay

// ---------------------------------------------------------------------------
__global__ void __launch_bounds__(RTPB, 6) render(const float* __restrict__ verts,
                                                  const int*   __restrict__ faces,
                                                  const float* __restrict__ tex,
                                                  const float* __restrict__ ref,
                                                  float*       __restrict__ out) {
    __shared__ float4 sQ[NFACES*3];     // 24 KB survivor coefficients
    __shared__ float  sR[NFACES];       // survivor 1/|denom|
    __shared__ short  sList[NFACES];    // survivor -> original face id
    __shared__ float4 sU[NVERTS];       // union: verts (phase1) / sBd,sLi (phase2+)
    __shared__ int    sCnt;
    __shared__ float  sWsum[8];

    float (*sBd)[64] = reinterpret_cast<float(*)[64]>(sU);                 // 2KB
    short (*sLi)[64] = reinterpret_cast<short(*)[64]>((char*)sU + 2048);   // 1KB

    const int tid  = threadIdx.x;
    const int bid  = blockIdx.x;
    const int lane = tid & 31, w = tid >> 5;

    // Tile geometry
    const int tileX = bid & (TPD-1), tileY = bid / TPD;
    const int c0 = tileX * TILE, r0 = tileY * TILE;
    const float SC = 2.0f / 256.0f;
    const float xc = (c0 + 4.0f) * SC - 1.0f;
    const float yc = 1.0f - (r0 + 4.0f) * SC;
    const float hx = 3.5f * SC, hy = 3.5f * SC;

    // Camera basis — compile-time constant-folded
    const float ex = 2.732f, ey = 0.0f, ez = -1.6728675276352844e-16f;
    const float nrm = sqrtf(ex*ex + ey*ey + ez*ez);
    const float zx = -ex/nrm, zy = -ey/nrm, zz = -ez/nrm;
    float xxu = zz, xyu = 0.f, xzu = -zx;
    const float xn = sqrtf(xxu*xxu + xyu*xyu + xzu*xzu);
    const float xx = xxu/xn, xy = xyu/xn, xz = xzu/xn;
    const float yx = zy*xz - zz*xy;
    const float yy = zz*xx - zx*xz;
    const float yz = zx*xy - zy*xx;

    if (tid == 0) sCnt = 0;

    // ========== Stage transformed vertices into SMEM ========================
    for (int v = tid; v < NVERTS; v += RTPB) {
        float vx = __ldg(&verts[3*v+0]) - ex;
        float vy = __ldg(&verts[3*v+1]) - ey;
        float vz = __ldg(&verts[3*v+2]) - ez;
        float X = vx*xx + vy*xy + vz*xz;
        float Y = vx*yx + vy*yy + vz*yz;
        float Z = vx*zx + vy*zy + vz*zz;
        sU[v] = make_float4(X, Y, Z, 0.f);
    }
    __syncthreads();

    // ========== Fused prep + cull, atomic compaction (no inner syncs) =======
    #pragma unroll
    for (int base = 0; base < NFACES; base += RTPB) {
        int f = base + tid;
        int i0 = __ldg(&faces[3*f+0]);
        int i1 = __ldg(&faces[3*f+1]);
        int i2 = __ldg(&faces[3*f+2]);

        float4 A = sU[i0];
        float4 B = sU[i1];
        float4 C = sU[i2];
        float ax = A.x, ay = A.y, az = A.z;
        float bx = B.x, by = B.y, bz = B.z;
        float cx = C.x, cy = C.y, cz = C.z;

        float denom = (bx-ax)*(cy-ay) - (by-ay)*(cx-ax);
        bool nondeg = fabsf(denom) > 1e-8f;
        float s = (denom > 0.f) ? 1.f : -1.f;

        float A0 = s*(by-cy), B0 = s*(cx-bx), C0 = s*((cy-by)*bx - (cx-bx)*by);
        float A1 = s*(cy-ay), B1 = s*(ax-cx), C1 = s*((ay-cy)*cx - (ax-cx)*cy);
        float A2 = s*(ay-by), B2 = s*(bx-ax), C2 = s*((by-ay)*ax - (bx-ax)*ay);

        // conservative per-tile max of each edge fn; reject if any < 0
        float u0m = fmaf(A0, xc, fmaf(B0, yc, C0)) + fabsf(A0)*hx + fabsf(B0)*hy;
        float u1m = fmaf(A1, xc, fmaf(B1, yc, C1)) + fabsf(A1)*hx + fabsf(B1)*hy;
        float u2m = fmaf(A2, xc, fmaf(B2, yc, C2)) + fabsf(A2)*hx + fabsf(B2)*hy;
        bool ov = nondeg & (u0m >= -1e-5f) & (u1m >= -1e-5f) & (u2m >= -1e-5f);

        unsigned m = __ballot_sync(0xFFFFFFFFu, ov);
        int wbase = 0;
        if (lane == 0 && m) wbase = atomicAdd(&sCnt, __popc(m));
        wbase = __shfl_sync(0xFFFFFFFFu, wbase, 0);
        if (ov) {
            // survivor-only: reciprocal + depth plane
            float r  = 1.0f / fabsf(denom);
            float D0 = az*r, D1 = bz*r, D2 = cz*r;
            float Dx = A0*D0 + A1*D1 + A2*D2;
            float Dy = B0*D0 + B1*D1 + B2*D2;
            float Dc = C0*D0 + C1*D1 + C2*D2;
            int pos = wbase + __popc(m & ((1u << lane) - 1u));
            sList[pos] = (short)f;
            sR[pos]    = r;
            sQ[pos*3+0] = make_float4(A0, B0, C0, A1);
            sQ[pos*3+1] = make_float4(B1, C1, A2, B2);
            sQ[pos*3+2] = make_float4(C2, Dx, Dy, Dc);
        }
    }
    __syncthreads();
    const int nf = sCnt;

    // ========== Phase 2: 8 warp-groups, 2 px/thread, contiguous eighths =====
    const int pcol = (lane & 3) << 1;
    const int prow = lane >> 2;
    const float px = (c0 + pcol + 0.5f) * SC - 1.0f;
    const float py = 1.0f - (r0 + prow + 0.5f) * SC;

    const int fBeg = (nf * w)     >> 3;
    const int fEnd = (nf * (w+1)) >> 3;

    float bd0 = __int_as_float(0x7f800000), bd1 = bd0;
    int   li0 = -1, li1 = -1;

    #pragma unroll 4
    for (int i = fBeg; i < fEnd; i++) {
        float4 q0 = sQ[i*3+0];
        float4 q1 = sQ[i*3+1];
        float4 q2 = sQ[i*3+2];
        float u0 = fmaf(q0.x, px, fmaf(q0.y, py, q0.z));
        float u1 = fmaf(q0.w, px, fmaf(q1.x, py, q1.y));
        float u2 = fmaf(q1.z, px, fmaf(q1.w, py, q2.x));
        float d0 = fmaf(q2.y, px, fmaf(q2.z, py, q2.w));
        float m0 = fminf(u0, fminf(u1, u2));
        if (m0 >= 0.f && d0 > 0.f && d0 < bd0) { bd0 = d0; li0 = i; }
        float v0 = fmaf(q0.x, SC, u0);
        float v1 = fmaf(q0.w, SC, u1);
        float v2 = fmaf(q1.z, SC, u2);
        float d1 = fmaf(q2.y, SC, d0);
        float m1 = fminf(v0, fminf(v1, v2));
        if (m1 >= 0.f && d1 > 0.f && d1 < bd1) { bd1 = d1; li1 = i; }
    }
    __syncthreads();                 // sU reads long done; reuse as sBd/sLi
    {
        int sub = prow * 8 + pcol;
        sBd[w][sub]   = bd0;  sLi[w][sub]   = (short)li0;
        sBd[w][sub+1] = bd1;  sLi[w][sub+1] = (short)li1;
    }
    __syncthreads();

    // ========== Epilogue: merge 8 candidates + shade + SSE ==================
    float acc = 0.f;
    if (tid < 64) {
        float best = sBd[0][tid];
        int   bli  = sLi[0][tid];
        #pragma unroll
        for (int g = 1; g < 8; g++) {
            float dg = sBd[g][tid];
            if (dg < best) { best = dg; bli = sLi[g][tid]; }
        }
        const float qx = (c0 + (tid & 7) + 0.5f) * SC - 1.0f;
        const float qy = 1.0f - (r0 + (tid >> 3) + 0.5f) * SC;
        const int   p  = (r0 + (tid >> 3)) * HW + (c0 + (tid & 7));

        float cc0 = 0.f, cc1 = 0.f, cc2 = 0.f;
        if (bli >= 0) {
            int fo = sList[bli];
            float4 q0 = sQ[bli*3+0];
            float4 q1 = sQ[bli*3+1];
            float  C2 = sQ[bli*3+2].x;
            float  r  = sR[bli];
            float u0 = fmaf(q0.x, qx, fmaf(q0.y, qy, q0.z));
            float u1 = fmaf(q0.w, qx, fmaf(q1.x, qy, q1.y));
            float u2 = fmaf(q1.z, qx, fmaf(q1.w, qy, C2));
            int t0 = min(max((int)rintf(u0 * r * 3.0f), 0), 3);
            int t1 = min(max((int)rintf(u1 * r * 3.0f), 0), 3);
            int t2 = min(max((int)rintf(u2 * r * 3.0f), 0), 3);
            int base = fo*192 + t0*48 + t1*12 + t2*3;
            cc0 = tanhf(__ldg(tex + base + 0));
            cc1 = tanhf(__ldg(tex + base + 1));
            cc2 = tanhf(__ldg(tex + base + 2));
        }
        float e0 = cc0 - __ldg(ref + p);
        float e1 = cc1 - __ldg(ref + p + NPIX);
        float e2 = cc2 - __ldg(ref + p + 2*NPIX);
        acc = fmaf(e0, e0, fmaf(e1, e1, e2*e2));
    }

    // ========== Block + grid reduction ======================================
    #pragma unroll
    for (int o = 16; o > 0; o >>= 1)
        acc += __shfl_down_sync(0xFFFFFFFFu, acc, o);
    if (lane == 0) sWsum[w] = acc;
    __syncthreads();

    __shared__ bool sLast;
    if (tid == 0) {
        g_partials[bid] = sWsum[0] + sWsum[1];
        __threadfence();
        unsigned t = atomicInc(&g_counter, RBLK - 1);   // wraps each replay
        sLast = (t == RBLK - 1);
    }
    __syncthreads();
    if (sLast) {
        float v = __ldcg(&g_partials[tid])
                + __ldcg(&g_partials[tid + 256])
                + __ldcg(&g_partials[tid + 512])
                + __ldcg(&g_partials[tid + 768]);
        #pragma unroll
        for (int o = 16; o > 0; o >>= 1)
            v += __shfl_down_sync(0xFFFFFFFFu, v, o);
        if (lane == 0) sWsum[w] = v;
        __syncthreads();
        if (tid == 0) {
            float s = 0.f;
            #pragma unroll
            for (int i = 0; i < 8; i++) s += sWsum[i];
            out[0] = s;
        }
    }
}

// ---------------------------------------------------------------------------
extern "C" void kernel_launch(void* const* d_in, const int* in_sizes, int n_in,
                              void* d_out, int out_size) {
    const float* verts = nullptr;
    const float* tex   = nullptr;
    const float* ref   = nullptr;
    const int*   faces = nullptr;
    for (int i = 0; i < n_in; i++) {
        switch (in_sizes[i]) {
            case 1926:   verts = (const float*)d_in[i]; break;
            case 98304:  tex   = (const float*)d_in[i]; break;
            case 196608: ref   = (const float*)d_in[i]; break;
            case 1536:   faces = (const int*)  d_in[i]; break;
            default: break;
        }
    }
    render<<<RBLK, RTPB>>>(verts, faces, tex, ref, (float*)d_out);
}